// round 1
// baseline (speedup 1.0000x reference)
#include <cuda_runtime.h>

// Problem constants (fixed by the dataset)
constexpr int NTOK = 4096;      // B*S = 4*1024
constexpr int E    = 512;
constexpr int C    = 512;
constexpr int H    = 1024;
constexpr int V    = 32000;
constexpr float EPS = 1e-5f;

// Scratch (allocation-free rule: __device__ globals)
__device__ float g_hbuf[NTOK * H];   // [ctx | tok] per token row
__device__ float g_h1[NTOK * H];
__device__ float g_h2[NTOK * H];

// ---------------------------------------------------------------------------
// Block-level reduction helper for LN (128 threads = 4 warps)
// ---------------------------------------------------------------------------
__device__ __forceinline__ void block_reduce_2(float& s, float& s2) {
    #pragma unroll
    for (int o = 16; o > 0; o >>= 1) {
        s  += __shfl_xor_sync(0xFFFFFFFFu, s,  o);
        s2 += __shfl_xor_sync(0xFFFFFFFFu, s2, o);
    }
    __shared__ float red[8];
    int wid = threadIdx.x >> 5;
    int lid = threadIdx.x & 31;
    if (lid == 0) { red[wid] = s; red[4 + wid] = s2; }
    __syncthreads();
    s  = red[0] + red[1] + red[2] + red[3];
    s2 = red[4] + red[5] + red[6] + red[7];
}

// ---------------------------------------------------------------------------
// Embedding gather + LayerNorm -> tok half of hbuf; zero the ctx half.
// One block of 128 threads per token; each thread owns one float4 (E=512).
// ---------------------------------------------------------------------------
__global__ void __launch_bounds__(128) embed_ln_kernel(
    const int* __restrict__ ids, const float* __restrict__ table,
    const float* __restrict__ g, const float* __restrict__ b)
{
    const int tok = blockIdx.x;
    const int tid = threadIdx.x;
    const long id = ids[tok];

    float4 x = reinterpret_cast<const float4*>(table + id * (long)E)[tid];
    float s  = x.x + x.y + x.z + x.w;
    float s2 = x.x * x.x + x.y * x.y + x.z * x.z + x.w * x.w;
    block_reduce_2(s, s2);

    const float mean = s * (1.0f / E);
    const float var  = s2 * (1.0f / E) - mean * mean;
    const float rstd = rsqrtf(var + EPS);

    float4 gg = reinterpret_cast<const float4*>(g)[tid];
    float4 bb = reinterpret_cast<const float4*>(b)[tid];
    float4 y;
    y.x = (x.x - mean) * rstd * gg.x + bb.x;
    y.y = (x.y - mean) * rstd * gg.y + bb.y;
    y.z = (x.z - mean) * rstd * gg.z + bb.z;
    y.w = (x.w - mean) * rstd * gg.w + bb.w;

    float* row = g_hbuf + (long)tok * H;
    reinterpret_cast<float4*>(row + C)[tid] = y;           // tok half
    reinterpret_cast<float4*>(row)[tid] = make_float4(0.f, 0.f, 0.f, 0.f); // ctx half
}

// ---------------------------------------------------------------------------
// Residual + LayerNorm, in place on hbuf halves.
// grid = (NTOK, 2): y==0 -> ctx half (cn params), y==1 -> tok half (tn params)
// ---------------------------------------------------------------------------
__global__ void __launch_bounds__(128) resid_ln_kernel(
    const float* __restrict__ cg, const float* __restrict__ cb,
    const float* __restrict__ tg, const float* __restrict__ tb)
{
    const int tok  = blockIdx.x;
    const int half = blockIdx.y;
    const int tid  = threadIdx.x;
    const float* g  = half ? tg : cg;
    const float* bp = half ? tb : cb;

    const long base = (long)tok * H + half * C;
    float4 a = reinterpret_cast<const float4*>(g_hbuf + base)[tid];
    float4 h = reinterpret_cast<const float4*>(g_h2 + base)[tid];
    float4 x;
    x.x = a.x + h.x; x.y = a.y + h.y; x.z = a.z + h.z; x.w = a.w + h.w;

    float s  = x.x + x.y + x.z + x.w;
    float s2 = x.x * x.x + x.y * x.y + x.z * x.z + x.w * x.w;
    block_reduce_2(s, s2);

    const float mean = s * (1.0f / C);
    const float var  = s2 * (1.0f / C) - mean * mean;
    const float rstd = rsqrtf(var + EPS);

    float4 gg = reinterpret_cast<const float4*>(g)[tid];
    float4 bb = reinterpret_cast<const float4*>(bp)[tid];
    float4 y;
    y.x = (x.x - mean) * rstd * gg.x + bb.x;
    y.y = (x.y - mean) * rstd * gg.y + bb.y;
    y.z = (x.z - mean) * rstd * gg.z + bb.z;
    y.w = (x.w - mean) * rstd * gg.w + bb.w;
    reinterpret_cast<float4*>(g_hbuf + base)[tid] = y;
}

// ---------------------------------------------------------------------------
// SGEMM: C[M,N] = A[M,K] * B[N,K]^T + bias[N], optional ReLU.
// A row-major (stride lda), B row-major (stride ldb) -> both K-contiguous.
// 128x128 block tile, BK=16, 256 threads, 8x8 per-thread micro-tile.
// All problem dims are exact multiples -> no bounds checks.
// ---------------------------------------------------------------------------
template <bool RELU>
__global__ void __launch_bounds__(256) sgemm_nt(
    const float* __restrict__ A, int lda,
    const float* __restrict__ B, int ldb,
    const float* __restrict__ bias,
    float* __restrict__ Cmat, long ldc, int K)
{
    constexpr int BM = 128, BN = 128, BK = 16;
    __shared__ float As[BK][BM + 4];
    __shared__ float Bs[BK][BN + 4];

    const int tid = threadIdx.x;
    const int tx = tid & 15;    // 0..15 -> N
    const int ty = tid >> 4;    // 0..15 -> M
    const long arow0 = (long)blockIdx.y * BM;
    const long brow0 = (long)blockIdx.x * BN;

    float acc[8][8];
    #pragma unroll
    for (int i = 0; i < 8; ++i)
        #pragma unroll
        for (int j = 0; j < 8; ++j) acc[i][j] = 0.0f;

    for (int k0 = 0; k0 < K; k0 += BK) {
        // cooperative tile load: 128 rows x 16 K = 512 float4s, 2 per thread
        #pragma unroll
        for (int p = 0; p < 2; ++p) {
            const int idx = p * 256 + tid;
            const int r   = idx >> 2;          // 0..127
            const int kg  = (idx & 3) << 2;    // 0,4,8,12
            float4 a = *reinterpret_cast<const float4*>(A + (arow0 + r) * lda + k0 + kg);
            As[kg + 0][r] = a.x; As[kg + 1][r] = a.y;
            As[kg + 2][r] = a.z; As[kg + 3][r] = a.w;
            float4 bv = *reinterpret_cast<const float4*>(B + (brow0 + r) * ldb + k0 + kg);
            Bs[kg + 0][r] = bv.x; Bs[kg + 1][r] = bv.y;
            Bs[kg + 2][r] = bv.z; Bs[kg + 3][r] = bv.w;
        }
        __syncthreads();

        #pragma unroll
        for (int k = 0; k < BK; ++k) {
            float4 a0 = *reinterpret_cast<const float4*>(&As[k][ty * 8]);
            float4 a1 = *reinterpret_cast<const float4*>(&As[k][ty * 8 + 4]);
            float4 b0 = *reinterpret_cast<const float4*>(&Bs[k][tx * 8]);
            float4 b1 = *reinterpret_cast<const float4*>(&Bs[k][tx * 8 + 4]);
            float ar[8] = {a0.x, a0.y, a0.z, a0.w, a1.x, a1.y, a1.z, a1.w};
            float br[8] = {b0.x, b0.y, b0.z, b0.w, b1.x, b1.y, b1.z, b1.w};
            #pragma unroll
            for (int i = 0; i < 8; ++i)
                #pragma unroll
                for (int j = 0; j < 8; ++j)
                    acc[i][j] = fmaf(ar[i], br[j], acc[i][j]);
        }
        __syncthreads();
    }

    // epilogue: bias (+ relu), vectorized stores
    float bs[8];
    #pragma unroll
    for (int j = 0; j < 8; ++j) bs[j] = bias[brow0 + tx * 8 + j];

    #pragma unroll
    for (int i = 0; i < 8; ++i) {
        const long row = arow0 + ty * 8 + i;
        float* cp = Cmat + row * ldc + brow0 + tx * 8;
        float v[8];
        #pragma unroll
        for (int j = 0; j < 8; ++j) {
            float o = acc[i][j] + bs[j];
            v[j] = RELU ? fmaxf(o, 0.0f) : o;
        }
        reinterpret_cast<float4*>(cp)[0] = make_float4(v[0], v[1], v[2], v[3]);
        reinterpret_cast<float4*>(cp)[1] = make_float4(v[4], v[5], v[6], v[7]);
    }
}

// ---------------------------------------------------------------------------
// Launch
// ---------------------------------------------------------------------------
extern "C" void kernel_launch(void* const* d_in, const int* in_sizes, int n_in,
                              void* d_out, int out_size)
{
    const int*   ids   = (const int*)  d_in[0];
    const float* table = (const float*)d_in[1];
    const float* en_g  = (const float*)d_in[2];
    const float* en_b  = (const float*)d_in[3];
    const float* Wb    = (const float*)d_in[4];   // [3,2,H,H]
    const float* bb    = (const float*)d_in[5];   // [3,2,H]
    const float* cn_g  = (const float*)d_in[6];   // [3,C]
    const float* cn_b  = (const float*)d_in[7];
    const float* tn_g  = (const float*)d_in[8];   // [3,E]
    const float* tn_b  = (const float*)d_in[9];
    const float* out_W = (const float*)d_in[10];  // [V,C]
    const float* out_b = (const float*)d_in[11];  // [V]
    float* logits = (float*)d_out;

    float *hbuf, *h1, *h2;
    cudaGetSymbolAddress((void**)&hbuf, g_hbuf);
    cudaGetSymbolAddress((void**)&h1,   g_h1);
    cudaGetSymbolAddress((void**)&h2,   g_h2);

    // 1) embedding + LN -> hbuf = [0 | tok]
    embed_ln_kernel<<<NTOK, 128>>>(ids, table, en_g, en_b);

    // 2) three residual blocks
    const dim3 fnn_grid(H / 128, NTOK / 128);   // (8, 32)
    for (int bi = 0; bi < 3; ++bi) {
        const float* W0 = Wb + (long)(bi * 2 + 0) * H * H;
        const float* W1 = Wb + (long)(bi * 2 + 1) * H * H;
        const float* b0 = bb + (bi * 2 + 0) * H;
        const float* b1 = bb + (bi * 2 + 1) * H;
        sgemm_nt<true><<<fnn_grid, 256>>>(hbuf, H, W0, H, b0, h1, H, H);
        sgemm_nt<true><<<fnn_grid, 256>>>(h1,   H, W1, H, b1, h2, H, H);
        resid_ln_kernel<<<dim3(NTOK, 2), 128>>>(cn_g + bi * C, cn_b + bi * C,
                                                tn_g + bi * E, tn_b + bi * E);
    }

    // 3) logits = tok @ out_W^T + out_b   (tok = hbuf[:, C:])
    const dim3 out_grid(V / 128, NTOK / 128);   // (250, 32)
    sgemm_nt<false><<<out_grid, 256>>>(hbuf + C, H, out_W, C, out_b,
                                       logits, V, C);
}

// round 3
// speedup vs baseline: 2.3317x; 2.3317x over previous
#include <cuda_runtime.h>
#include <cuda_bf16.h>
#include <cstdint>

// Problem constants (fixed by the dataset)
constexpr int NTOK = 4096;      // B*S = 4*1024
constexpr int E    = 512;
constexpr int C    = 512;
constexpr int H    = 1024;
constexpr int V    = 32000;
constexpr float EPS = 1e-5f;

constexpr int W_ELEMS  = 3 * 2 * H * H;
constexpr int OW_ELEMS = V * C;

// GEMM tiling: 128x128x64, 256 threads, warp tile 64x32 (2x4 warp grid)
constexpr int BM = 128, BN = 128, BK = 64;
constexpr int TILE_B  = BM * BK * 2;              // 16384 bytes (one split of A or B)
constexpr int STAGE   = 4 * TILE_B;               // Ahi|Alo|Bhi|Blo = 65536
constexpr int SMEM_SZ = 2 * STAGE;                // 131072

// Scratch (allocation-free rule: __device__ globals)
__device__ float g_hbuf[NTOK * H];
__device__ float g_h2[NTOK * H];
__device__ __nv_bfloat16 g_xhi[NTOK * H], g_xlo[NTOK * H];
__device__ __nv_bfloat16 g_yhi[NTOK * H], g_ylo[NTOK * H];
__device__ __nv_bfloat16 g_whi[W_ELEMS],  g_wlo[W_ELEMS];
__device__ __nv_bfloat16 g_owhi[OW_ELEMS], g_owlo[OW_ELEMS];

// ---------------------------------------------------------------------------
// PTX helpers
// ---------------------------------------------------------------------------
__device__ __forceinline__ uint32_t cvta_smem(const void* p) {
    uint32_t a;
    asm("{\n\t.reg .u64 t;\n\tcvta.to.shared.u64 t, %1;\n\tcvt.u32.u64 %0, t;\n\t}"
        : "=r"(a) : "l"(p));
    return a;
}
__device__ __forceinline__ uint32_t swz(uint32_t o) { return o ^ ((o >> 3) & 0x70); }

__device__ __forceinline__ void cp16(uint32_t dst, const void* src) {
    asm volatile("cp.async.cg.shared.global [%0], [%1], 16;" :: "r"(dst), "l"(src));
}
__device__ __forceinline__ void cp_commit() {
    asm volatile("cp.async.commit_group;" ::: "memory");
}

__device__ __forceinline__ void ldsm4(uint32_t* r, uint32_t addr) {
    asm volatile("ldmatrix.sync.aligned.m8n8.x4.shared.b16 {%0,%1,%2,%3}, [%4];"
                 : "=r"(r[0]), "=r"(r[1]), "=r"(r[2]), "=r"(r[3]) : "r"(addr));
}

__device__ __forceinline__ void mma16816(float* d, const uint32_t* a,
                                         uint32_t b0, uint32_t b1) {
    asm volatile(
        "mma.sync.aligned.m16n8k16.row.col.f32.bf16.bf16.f32 "
        "{%0,%1,%2,%3}, {%4,%5,%6,%7}, {%8,%9}, {%0,%1,%2,%3};"
        : "+f"(d[0]), "+f"(d[1]), "+f"(d[2]), "+f"(d[3])
        : "r"(a[0]), "r"(a[1]), "r"(a[2]), "r"(a[3]), "r"(b0), "r"(b1));
}

__device__ __forceinline__ void split2(float a, float b, uint32_t& hi, uint32_t& lo) {
    __nv_bfloat16 ha = __float2bfloat16_rn(a), hb = __float2bfloat16_rn(b);
    __nv_bfloat16 la = __float2bfloat16_rn(a - __bfloat162float(ha));
    __nv_bfloat16 lb = __float2bfloat16_rn(b - __bfloat162float(hb));
    hi = (uint32_t)__bfloat16_as_ushort(ha) | ((uint32_t)__bfloat16_as_ushort(hb) << 16);
    lo = (uint32_t)__bfloat16_as_ushort(la) | ((uint32_t)__bfloat16_as_ushort(lb) << 16);
}

// ---------------------------------------------------------------------------
// fp32 -> (bf16 hi, bf16 lo) elementwise split (weights)
// ---------------------------------------------------------------------------
__global__ void __launch_bounds__(256) f32_to_bf16pair(
    const float4* __restrict__ src, uint2* __restrict__ hi, uint2* __restrict__ lo, int n4)
{
    const int i = blockIdx.x * 256 + threadIdx.x;
    if (i >= n4) return;
    const float4 x = src[i];
    uint32_t h0, l0, h1, l1;
    split2(x.x, x.y, h0, l0);
    split2(x.z, x.w, h1, l1);
    hi[i] = make_uint2(h0, h1);
    lo[i] = make_uint2(l0, l1);
}

// ---------------------------------------------------------------------------
// LN reduction helper (128 threads = 4 warps)
// ---------------------------------------------------------------------------
__device__ __forceinline__ void block_reduce_2(float& s, float& s2) {
    #pragma unroll
    for (int o = 16; o > 0; o >>= 1) {
        s  += __shfl_xor_sync(0xFFFFFFFFu, s,  o);
        s2 += __shfl_xor_sync(0xFFFFFFFFu, s2, o);
    }
    __shared__ float red[8];
    int wid = threadIdx.x >> 5;
    int lid = threadIdx.x & 31;
    if (lid == 0) { red[wid] = s; red[4 + wid] = s2; }
    __syncthreads();
    s  = red[0] + red[1] + red[2] + red[3];
    s2 = red[4] + red[5] + red[6] + red[7];
}

// ---------------------------------------------------------------------------
// Embedding gather + LN -> hbuf fp32 [0|tok] and x hi/lo bf16 (full row)
// ---------------------------------------------------------------------------
__global__ void __launch_bounds__(128) embed_ln_kernel(
    const int* __restrict__ ids, const float* __restrict__ table,
    const float* __restrict__ g, const float* __restrict__ b)
{
    const int tok = blockIdx.x;
    const int tid = threadIdx.x;
    const long id = ids[tok];

    float4 x = reinterpret_cast<const float4*>(table + id * (long)E)[tid];
    float s  = x.x + x.y + x.z + x.w;
    float s2 = x.x * x.x + x.y * x.y + x.z * x.z + x.w * x.w;
    block_reduce_2(s, s2);

    const float mean = s * (1.0f / E);
    const float var  = s2 * (1.0f / E) - mean * mean;
    const float rstd = rsqrtf(var + EPS);

    float4 gg = reinterpret_cast<const float4*>(g)[tid];
    float4 bb = reinterpret_cast<const float4*>(b)[tid];
    float4 y;
    y.x = (x.x - mean) * rstd * gg.x + bb.x;
    y.y = (x.y - mean) * rstd * gg.y + bb.y;
    y.z = (x.z - mean) * rstd * gg.z + bb.z;
    y.w = (x.w - mean) * rstd * gg.w + bb.w;

    const long rbase = (long)tok * H;
    float* row = g_hbuf + rbase;
    reinterpret_cast<float4*>(row + C)[tid] = y;
    reinterpret_cast<float4*>(row)[tid] = make_float4(0.f, 0.f, 0.f, 0.f);

    uint32_t h0, l0, h1, l1;
    split2(y.x, y.y, h0, l0);
    split2(y.z, y.w, h1, l1);
    reinterpret_cast<uint2*>(g_xhi + rbase + C)[tid] = make_uint2(h0, h1);
    reinterpret_cast<uint2*>(g_xlo + rbase + C)[tid] = make_uint2(l0, l1);
    reinterpret_cast<uint2*>(g_xhi + rbase)[tid] = make_uint2(0, 0);
    reinterpret_cast<uint2*>(g_xlo + rbase)[tid] = make_uint2(0, 0);
}

// ---------------------------------------------------------------------------
// Residual + LN; writes hbuf fp32 and x hi/lo bf16
// ---------------------------------------------------------------------------
__global__ void __launch_bounds__(128) resid_ln_kernel(
    const float* __restrict__ cg, const float* __restrict__ cb,
    const float* __restrict__ tg, const float* __restrict__ tb)
{
    const int tok  = blockIdx.x;
    const int half = blockIdx.y;
    const int tid  = threadIdx.x;
    const float* g  = half ? tg : cg;
    const float* bp = half ? tb : cb;

    const long base = (long)tok * H + half * C;
    float4 a = reinterpret_cast<const float4*>(g_hbuf + base)[tid];
    float4 h = reinterpret_cast<const float4*>(g_h2 + base)[tid];
    float4 x;
    x.x = a.x + h.x; x.y = a.y + h.y; x.z = a.z + h.z; x.w = a.w + h.w;

    float s  = x.x + x.y + x.z + x.w;
    float s2 = x.x * x.x + x.y * x.y + x.z * x.z + x.w * x.w;
    block_reduce_2(s, s2);

    const float mean = s * (1.0f / C);
    const float var  = s2 * (1.0f / C) - mean * mean;
    const float rstd = rsqrtf(var + EPS);

    float4 gg = reinterpret_cast<const float4*>(g)[tid];
    float4 bb = reinterpret_cast<const float4*>(bp)[tid];
    float4 y;
    y.x = (x.x - mean) * rstd * gg.x + bb.x;
    y.y = (x.y - mean) * rstd * gg.y + bb.y;
    y.z = (x.z - mean) * rstd * gg.z + bb.z;
    y.w = (x.w - mean) * rstd * gg.w + bb.w;
    reinterpret_cast<float4*>(g_hbuf + base)[tid] = y;

    uint32_t h0, l0, h1, l1;
    split2(y.x, y.y, h0, l0);
    split2(y.z, y.w, h1, l1);
    reinterpret_cast<uint2*>(g_xhi + base)[tid] = make_uint2(h0, h1);
    reinterpret_cast<uint2*>(g_xlo + base)[tid] = make_uint2(l0, l1);
}

// ---------------------------------------------------------------------------
// bf16x3 split GEMM on mma.sync: D[M,N] = A[M,K] @ B[N,K]^T + bias
// A,B as (hi,lo) bf16 pairs, K-contiguous. fp32 accumulate.
// 128x128x64 tile, cp.async double-buffered, SW128-swizzled smem, ldmatrix.
// OUT_MODE 0: fp32 out. OUT_MODE 1: bf16 hi/lo out.
// ---------------------------------------------------------------------------
template <bool RELU, int OUT_MODE>
__global__ void __launch_bounds__(256, 1) gemm_mma(
    const __nv_bfloat16* __restrict__ Ahi, const __nv_bfloat16* __restrict__ Alo, int lda,
    const __nv_bfloat16* __restrict__ Bhi, const __nv_bfloat16* __restrict__ Blo, int ldb,
    const float* __restrict__ bias,
    float* __restrict__ Cf,
    __nv_bfloat16* __restrict__ Chi, __nv_bfloat16* __restrict__ Clo,
    int ldc, int K)
{
    extern __shared__ char smem[];
    const uint32_t sb = cvta_smem(smem);
    const int tid = threadIdx.x;
    const int w   = tid >> 5;
    const int l   = tid & 31;
    const int wm  = (w >> 2) * 64;     // warp M origin in tile
    const int wn  = (w & 3) * 32;      // warp N origin in tile
    const long m0 = (long)blockIdx.y * BM;
    const long n0 = (long)blockIdx.x * BN;

    // lane-derived ldmatrix addressing
    const int lrow  = ((l >> 3) & 1) * 8 + (l & 7);   // row within 16-row frag
    const int lkseg = ((l >> 4) & 1) * 16;            // 0 or 16 bytes (k 8-16)

    const int NC = K >> 6;

    auto load_chunk = [&](int c, int stage) {
        const int k0 = c << 6;
        const uint32_t sbase = sb + (uint32_t)stage * STAGE;
        #pragma unroll
        for (int it = 0; it < 4; ++it) {
            const int idx = it * 256 + tid;
            const int r = idx >> 3, ch = idx & 7;
            const uint32_t so = swz((uint32_t)(r * 128 + ch * 16));
            const long ga = (m0 + r) * (long)lda + k0 + ch * 8;
            const long gb = (n0 + r) * (long)ldb + k0 + ch * 8;
            cp16(sbase + so,              Ahi + ga);
            cp16(sbase + TILE_B + so,     Alo + ga);
            cp16(sbase + 2 * TILE_B + so, Bhi + gb);
            cp16(sbase + 3 * TILE_B + so, Blo + gb);
        }
    };

    float acc[4][4][4];
    #pragma unroll
    for (int i = 0; i < 4; ++i)
        #pragma unroll
        for (int j = 0; j < 4; ++j)
            #pragma unroll
            for (int q = 0; q < 4; ++q) acc[i][j][q] = 0.0f;

    load_chunk(0, 0); cp_commit();
    load_chunk(1, 1); cp_commit();

    for (int c = 0; c < NC; ++c) {
        if (c + 1 < NC) asm volatile("cp.async.wait_group 1;" ::: "memory");
        else            asm volatile("cp.async.wait_group 0;" ::: "memory");
        __syncthreads();

        const uint32_t sbase = sb + (uint32_t)(c & 1) * STAGE;
        #pragma unroll
        for (int ks = 0; ks < 4; ++ks) {
            uint32_t Ah[4][4], Al[4][4], Bh[2][4], Bl[2][4];
            const int kb = ks * 32 + lkseg;
            #pragma unroll
            for (int mf = 0; mf < 4; ++mf) {
                const uint32_t off = swz((uint32_t)((wm + mf * 16 + lrow) * 128 + kb));
                ldsm4(Ah[mf], sbase + off);
                ldsm4(Al[mf], sbase + TILE_B + off);
            }
            #pragma unroll
            for (int nf2 = 0; nf2 < 2; ++nf2) {
                const uint32_t off = swz((uint32_t)((wn + nf2 * 16 + lrow) * 128 + kb));
                ldsm4(Bh[nf2], sbase + 2 * TILE_B + off);
                ldsm4(Bl[nf2], sbase + 3 * TILE_B + off);
            }
            #pragma unroll
            for (int mf = 0; mf < 4; ++mf) {
                #pragma unroll
                for (int nf = 0; nf < 4; ++nf) {
                    const int p = nf >> 1, q = nf & 1;
                    mma16816(acc[mf][nf], Ah[mf], Bh[p][q], Bh[p][q + 2]);
                    mma16816(acc[mf][nf], Ah[mf], Bl[p][q], Bl[p][q + 2]);
                    mma16816(acc[mf][nf], Al[mf], Bh[p][q], Bh[p][q + 2]);
                }
            }
        }
        __syncthreads();
        if (c + 2 < NC) { load_chunk(c + 2, c & 1); cp_commit(); }
    }

    // Epilogue
    const int tig = l & 3, grp = l >> 2;
    #pragma unroll
    for (int nf = 0; nf < 4; ++nf) {
        const long col = n0 + wn + nf * 8 + 2 * tig;
        const float b0 = bias[col], b1 = bias[col + 1];
        #pragma unroll
        for (int mf = 0; mf < 4; ++mf) {
            const long r0 = m0 + wm + mf * 16 + grp;
            float v00 = acc[mf][nf][0] + b0, v01 = acc[mf][nf][1] + b1;
            float v10 = acc[mf][nf][2] + b0, v11 = acc[mf][nf][3] + b1;
            if (RELU) {
                v00 = fmaxf(v00, 0.f); v01 = fmaxf(v01, 0.f);
                v10 = fmaxf(v10, 0.f); v11 = fmaxf(v11, 0.f);
            }
            if (OUT_MODE == 0) {
                *reinterpret_cast<float2*>(Cf + r0 * (long)ldc + col) = make_float2(v00, v01);
                *reinterpret_cast<float2*>(Cf + (r0 + 8) * (long)ldc + col) = make_float2(v10, v11);
            } else {
                uint32_t h0, lo0, h1, lo1;
                split2(v00, v01, h0, lo0);
                split2(v10, v11, h1, lo1);
                *reinterpret_cast<uint32_t*>(Chi + r0 * (long)ldc + col) = h0;
                *reinterpret_cast<uint32_t*>(Clo + r0 * (long)ldc + col) = lo0;
                *reinterpret_cast<uint32_t*>(Chi + (r0 + 8) * (long)ldc + col) = h1;
                *reinterpret_cast<uint32_t*>(Clo + (r0 + 8) * (long)ldc + col) = lo1;
            }
        }
    }
}

// ---------------------------------------------------------------------------
// Launch
// ---------------------------------------------------------------------------
extern "C" void kernel_launch(void* const* d_in, const int* in_sizes, int n_in,
                              void* d_out, int out_size)
{
    const int*   ids   = (const int*)  d_in[0];
    const float* table = (const float*)d_in[1];
    const float* en_g  = (const float*)d_in[2];
    const float* en_b  = (const float*)d_in[3];
    const float* Wb    = (const float*)d_in[4];
    const float* bb    = (const float*)d_in[5];
    const float* cn_g  = (const float*)d_in[6];
    const float* cn_b  = (const float*)d_in[7];
    const float* tn_g  = (const float*)d_in[8];
    const float* tn_b  = (const float*)d_in[9];
    const float* out_W = (const float*)d_in[10];
    const float* out_b = (const float*)d_in[11];
    float* logits = (float*)d_out;

    __nv_bfloat16 *xhi, *xlo, *yhi, *ylo, *whi, *wlo, *owhi, *owlo;
    float *h2;
    cudaGetSymbolAddress((void**)&xhi,  g_xhi);
    cudaGetSymbolAddress((void**)&xlo,  g_xlo);
    cudaGetSymbolAddress((void**)&yhi,  g_yhi);
    cudaGetSymbolAddress((void**)&ylo,  g_ylo);
    cudaGetSymbolAddress((void**)&whi,  g_whi);
    cudaGetSymbolAddress((void**)&wlo,  g_wlo);
    cudaGetSymbolAddress((void**)&owhi, g_owhi);
    cudaGetSymbolAddress((void**)&owlo, g_owlo);
    cudaGetSymbolAddress((void**)&h2,   g_h2);

    cudaFuncSetAttribute(gemm_mma<true, 1>,  cudaFuncAttributeMaxDynamicSharedMemorySize, SMEM_SZ);
    cudaFuncSetAttribute(gemm_mma<true, 0>,  cudaFuncAttributeMaxDynamicSharedMemorySize, SMEM_SZ);
    cudaFuncSetAttribute(gemm_mma<false, 0>, cudaFuncAttributeMaxDynamicSharedMemorySize, SMEM_SZ);

    // 1) split weights into bf16 hi/lo
    f32_to_bf16pair<<<W_ELEMS / 4 / 256, 256>>>(
        (const float4*)Wb, (uint2*)whi, (uint2*)wlo, W_ELEMS / 4);
    f32_to_bf16pair<<<OW_ELEMS / 4 / 256, 256>>>(
        (const float4*)out_W, (uint2*)owhi, (uint2*)owlo, OW_ELEMS / 4);

    // 2) embedding + LN
    embed_ln_kernel<<<NTOK, 128>>>(ids, table, en_g, en_b);

    // 3) three residual blocks
    const dim3 fnn_grid(H / BN, NTOK / BM);           // (8, 32)
    for (int bi = 0; bi < 3; ++bi) {
        const __nv_bfloat16* W0h = whi + (long)(bi * 2 + 0) * H * H;
        const __nv_bfloat16* W0l = wlo + (long)(bi * 2 + 0) * H * H;
        const __nv_bfloat16* W1h = whi + (long)(bi * 2 + 1) * H * H;
        const __nv_bfloat16* W1l = wlo + (long)(bi * 2 + 1) * H * H;
        const float* b0 = bb + (bi * 2 + 0) * H;
        const float* b1 = bb + (bi * 2 + 1) * H;

        gemm_mma<true, 1><<<fnn_grid, 256, SMEM_SZ>>>(
            xhi, xlo, H, W0h, W0l, H, b0,
            (float*)nullptr, yhi, ylo, H, H);
        gemm_mma<true, 0><<<fnn_grid, 256, SMEM_SZ>>>(
            yhi, ylo, H, W1h, W1l, H, b1,
            h2, (__nv_bfloat16*)nullptr, (__nv_bfloat16*)nullptr, H, H);
        resid_ln_kernel<<<dim3(NTOK, 2), 128>>>(cn_g + bi * C, cn_b + bi * C,
                                                tn_g + bi * E, tn_b + bi * E);
    }

    // 4) logits = tok @ out_W^T + out_b
    const dim3 out_grid(V / BN, NTOK / BM);           // (250, 32)
    gemm_mma<false, 0><<<out_grid, 256, SMEM_SZ>>>(
        xhi + C, xlo + C, H, owhi, owlo, C, out_b,
        logits, (__nv_bfloat16*)nullptr, (__nv_bfloat16*)nullptr, V, C);
}

// round 4
// speedup vs baseline: 2.4146x; 1.0356x over previous
#include <cuda_runtime.h>
#include <cuda_bf16.h>
#include <cstdint>

// Problem constants (fixed by the dataset)
constexpr int NTOK = 4096;      // B*S = 4*1024
constexpr int E    = 512;
constexpr int C    = 512;
constexpr int H    = 1024;
constexpr int V    = 32000;
constexpr float EPS = 1e-5f;

constexpr int W_ELEMS  = 3 * 2 * H * H;
constexpr int OW_ELEMS = V * C;

// GEMM tiling: 128x128x64, 256 threads, warp tile 64x32 (2x4 warp grid)
constexpr int BM = 128, BN = 128, BK = 64;
constexpr int TILE_B  = BM * BK * 2;              // 16384 bytes (one split of A or B)
constexpr int STAGE   = 4 * TILE_B;               // Ahi|Alo|Bhi|Blo = 65536
constexpr int STAGES  = 3;
constexpr int SMEM_SZ = STAGES * STAGE;           // 196608

// Scratch (allocation-free rule: __device__ globals)
__device__ float g_hbuf[NTOK * H];
__device__ float g_h2[NTOK * H];
__device__ __nv_bfloat16 g_xhi[NTOK * H], g_xlo[NTOK * H];
__device__ __nv_bfloat16 g_yhi[NTOK * H], g_ylo[NTOK * H];
__device__ __nv_bfloat16 g_whi[W_ELEMS],  g_wlo[W_ELEMS];
__device__ __nv_bfloat16 g_owhi[OW_ELEMS], g_owlo[OW_ELEMS];

// ---------------------------------------------------------------------------
// PTX helpers
// ---------------------------------------------------------------------------
__device__ __forceinline__ uint32_t cvta_smem(const void* p) {
    uint32_t a;
    asm("{\n\t.reg .u64 t;\n\tcvta.to.shared.u64 t, %1;\n\tcvt.u32.u64 %0, t;\n\t}"
        : "=r"(a) : "l"(p));
    return a;
}
__device__ __forceinline__ uint32_t swz(uint32_t o) { return o ^ ((o >> 3) & 0x70); }

__device__ __forceinline__ void cp16(uint32_t dst, const void* src) {
    asm volatile("cp.async.cg.shared.global [%0], [%1], 16;" :: "r"(dst), "l"(src));
}
__device__ __forceinline__ void cp_commit() {
    asm volatile("cp.async.commit_group;" ::: "memory");
}

__device__ __forceinline__ void ldsm4(uint32_t* r, uint32_t addr) {
    asm volatile("ldmatrix.sync.aligned.m8n8.x4.shared.b16 {%0,%1,%2,%3}, [%4];"
                 : "=r"(r[0]), "=r"(r[1]), "=r"(r[2]), "=r"(r[3]) : "r"(addr));
}

__device__ __forceinline__ void mma16816(float* d, const uint32_t* a,
                                         uint32_t b0, uint32_t b1) {
    asm volatile(
        "mma.sync.aligned.m16n8k16.row.col.f32.bf16.bf16.f32 "
        "{%0,%1,%2,%3}, {%4,%5,%6,%7}, {%8,%9}, {%0,%1,%2,%3};"
        : "+f"(d[0]), "+f"(d[1]), "+f"(d[2]), "+f"(d[3])
        : "r"(a[0]), "r"(a[1]), "r"(a[2]), "r"(a[3]), "r"(b0), "r"(b1));
}

__device__ __forceinline__ void split2(float a, float b, uint32_t& hi, uint32_t& lo) {
    __nv_bfloat16 ha = __float2bfloat16_rn(a), hb = __float2bfloat16_rn(b);
    __nv_bfloat16 la = __float2bfloat16_rn(a - __bfloat162float(ha));
    __nv_bfloat16 lb = __float2bfloat16_rn(b - __bfloat162float(hb));
    hi = (uint32_t)__bfloat16_as_ushort(ha) | ((uint32_t)__bfloat16_as_ushort(hb) << 16);
    lo = (uint32_t)__bfloat16_as_ushort(la) | ((uint32_t)__bfloat16_as_ushort(lb) << 16);
}

// ---------------------------------------------------------------------------
// fp32 -> (bf16 hi, bf16 lo) elementwise split (weights)
// ---------------------------------------------------------------------------
__global__ void __launch_bounds__(256) f32_to_bf16pair(
    const float4* __restrict__ src, uint2* __restrict__ hi, uint2* __restrict__ lo, int n4)
{
    const int i = blockIdx.x * 256 + threadIdx.x;
    if (i >= n4) return;
    const float4 x = src[i];
    uint32_t h0, l0, h1, l1;
    split2(x.x, x.y, h0, l0);
    split2(x.z, x.w, h1, l1);
    hi[i] = make_uint2(h0, h1);
    lo[i] = make_uint2(l0, l1);
}

// ---------------------------------------------------------------------------
// LN reduction helper (128 threads = 4 warps)
// ---------------------------------------------------------------------------
__device__ __forceinline__ void block_reduce_2(float& s, float& s2) {
    #pragma unroll
    for (int o = 16; o > 0; o >>= 1) {
        s  += __shfl_xor_sync(0xFFFFFFFFu, s,  o);
        s2 += __shfl_xor_sync(0xFFFFFFFFu, s2, o);
    }
    __shared__ float red[8];
    int wid = threadIdx.x >> 5;
    int lid = threadIdx.x & 31;
    if (lid == 0) { red[wid] = s; red[4 + wid] = s2; }
    __syncthreads();
    s  = red[0] + red[1] + red[2] + red[3];
    s2 = red[4] + red[5] + red[6] + red[7];
}

// ---------------------------------------------------------------------------
// Embedding gather + LN -> hbuf fp32 [0|tok] and x hi/lo bf16 (full row)
// ---------------------------------------------------------------------------
__global__ void __launch_bounds__(128) embed_ln_kernel(
    const int* __restrict__ ids, const float* __restrict__ table,
    const float* __restrict__ g, const float* __restrict__ b)
{
    const int tok = blockIdx.x;
    const int tid = threadIdx.x;
    const long id = ids[tok];

    float4 x = reinterpret_cast<const float4*>(table + id * (long)E)[tid];
    float s  = x.x + x.y + x.z + x.w;
    float s2 = x.x * x.x + x.y * x.y + x.z * x.z + x.w * x.w;
    block_reduce_2(s, s2);

    const float mean = s * (1.0f / E);
    const float var  = s2 * (1.0f / E) - mean * mean;
    const float rstd = rsqrtf(var + EPS);

    float4 gg = reinterpret_cast<const float4*>(g)[tid];
    float4 bb = reinterpret_cast<const float4*>(b)[tid];
    float4 y;
    y.x = (x.x - mean) * rstd * gg.x + bb.x;
    y.y = (x.y - mean) * rstd * gg.y + bb.y;
    y.z = (x.z - mean) * rstd * gg.z + bb.z;
    y.w = (x.w - mean) * rstd * gg.w + bb.w;

    const long rbase = (long)tok * H;
    float* row = g_hbuf + rbase;
    reinterpret_cast<float4*>(row + C)[tid] = y;
    reinterpret_cast<float4*>(row)[tid] = make_float4(0.f, 0.f, 0.f, 0.f);

    uint32_t h0, l0, h1, l1;
    split2(y.x, y.y, h0, l0);
    split2(y.z, y.w, h1, l1);
    reinterpret_cast<uint2*>(g_xhi + rbase + C)[tid] = make_uint2(h0, h1);
    reinterpret_cast<uint2*>(g_xlo + rbase + C)[tid] = make_uint2(l0, l1);
    reinterpret_cast<uint2*>(g_xhi + rbase)[tid] = make_uint2(0, 0);
    reinterpret_cast<uint2*>(g_xlo + rbase)[tid] = make_uint2(0, 0);
}

// ---------------------------------------------------------------------------
// Residual + LN; writes hbuf fp32 and x hi/lo bf16
// ---------------------------------------------------------------------------
__global__ void __launch_bounds__(128) resid_ln_kernel(
    const float* __restrict__ cg, const float* __restrict__ cb,
    const float* __restrict__ tg, const float* __restrict__ tb)
{
    const int tok  = blockIdx.x;
    const int half = blockIdx.y;
    const int tid  = threadIdx.x;
    const float* g  = half ? tg : cg;
    const float* bp = half ? tb : cb;

    const long base = (long)tok * H + half * C;
    float4 a = reinterpret_cast<const float4*>(g_hbuf + base)[tid];
    float4 h = reinterpret_cast<const float4*>(g_h2 + base)[tid];
    float4 x;
    x.x = a.x + h.x; x.y = a.y + h.y; x.z = a.z + h.z; x.w = a.w + h.w;

    float s  = x.x + x.y + x.z + x.w;
    float s2 = x.x * x.x + x.y * x.y + x.z * x.z + x.w * x.w;
    block_reduce_2(s, s2);

    const float mean = s * (1.0f / C);
    const float var  = s2 * (1.0f / C) - mean * mean;
    const float rstd = rsqrtf(var + EPS);

    float4 gg = reinterpret_cast<const float4*>(g)[tid];
    float4 bb = reinterpret_cast<const float4*>(bp)[tid];
    float4 y;
    y.x = (x.x - mean) * rstd * gg.x + bb.x;
    y.y = (x.y - mean) * rstd * gg.y + bb.y;
    y.z = (x.z - mean) * rstd * gg.z + bb.z;
    y.w = (x.w - mean) * rstd * gg.w + bb.w;
    reinterpret_cast<float4*>(g_hbuf + base)[tid] = y;

    uint32_t h0, l0, h1, l1;
    split2(y.x, y.y, h0, l0);
    split2(y.z, y.w, h1, l1);
    reinterpret_cast<uint2*>(g_xhi + base)[tid] = make_uint2(h0, h1);
    reinterpret_cast<uint2*>(g_xlo + base)[tid] = make_uint2(l0, l1);
}

// ---------------------------------------------------------------------------
// bf16x3 split GEMM on mma.sync: D[M,N] = A[M,K] @ B[N,K]^T + bias
// 3-stage cp.async pipeline, one barrier per chunk, loads interleaved into
// the k-loop, register double-buffered ldmatrix fragments.
// OUT_MODE 0: fp32 out. OUT_MODE 1: bf16 hi/lo out.
// ---------------------------------------------------------------------------
template <bool RELU, int OUT_MODE>
__global__ void __launch_bounds__(256, 1) gemm_mma(
    const __nv_bfloat16* __restrict__ Ahi, const __nv_bfloat16* __restrict__ Alo, int lda,
    const __nv_bfloat16* __restrict__ Bhi, const __nv_bfloat16* __restrict__ Blo, int ldb,
    const float* __restrict__ bias,
    float* __restrict__ Cf,
    __nv_bfloat16* __restrict__ Chi, __nv_bfloat16* __restrict__ Clo,
    int ldc, int K)
{
    extern __shared__ char smem[];
    const uint32_t sb = cvta_smem(smem);
    const int tid = threadIdx.x;
    const int w   = tid >> 5;
    const int l   = tid & 31;
    const int wm  = (w >> 2) * 64;
    const int wn  = (w & 3) * 32;
    const long m0 = (long)blockIdx.y * BM;
    const long n0 = (long)blockIdx.x * BN;

    const int lrow  = ((l >> 3) & 1) * 8 + (l & 7);
    const int lkseg = ((l >> 4) & 1) * 16;

    const int NC = K >> 6;

    // per-thread precomputed load indices (16 cp16 per chunk, 4 per part)
    const int ldr = tid >> 3;             // row 0..31 within 32-row group? no: 0..31
    const int ldc8 = (tid & 7) * 8;       // k element offset
    // full row index r = (it*256+tid)>>3 = it*32 + (tid>>3)
    const uint32_t so_base = (uint32_t)(ldr * 128 + (tid & 7) * 16);

    auto load_part = [&](int c, uint32_t sbase, int it) {
        const int k0 = c << 6;
        const int r = it * 32 + ldr;
        const uint32_t so = swz((uint32_t)(r * 128) + (uint32_t)((tid & 7) * 16));
        const long ga = (m0 + r) * (long)lda + k0 + ldc8;
        const long gb = (n0 + r) * (long)ldb + k0 + ldc8;
        cp16(sbase + so,              Ahi + ga);
        cp16(sbase + TILE_B + so,     Alo + ga);
        cp16(sbase + 2 * TILE_B + so, Bhi + gb);
        cp16(sbase + 3 * TILE_B + so, Blo + gb);
    };
    auto load_chunk = [&](int c, int stage) {
        const uint32_t sbase = sb + (uint32_t)stage * STAGE;
        #pragma unroll
        for (int it = 0; it < 4; ++it) load_part(c, sbase, it);
    };

    float acc[4][4][4];
    #pragma unroll
    for (int i = 0; i < 4; ++i)
        #pragma unroll
        for (int j = 0; j < 4; ++j)
            #pragma unroll
            for (int q = 0; q < 4; ++q) acc[i][j][q] = 0.0f;

    // fragment double buffers
    uint32_t Ah[2][4][4], Al[2][4][4], Bh[2][2][4], Bl[2][2][4];

    auto ld_frag = [&](int buf, uint32_t sbase, int ks) {
        const int kb = ks * 32 + lkseg;
        #pragma unroll
        for (int mf = 0; mf < 4; ++mf) {
            const uint32_t off = swz((uint32_t)((wm + mf * 16 + lrow) * 128 + kb));
            ldsm4(Ah[buf][mf], sbase + off);
            ldsm4(Al[buf][mf], sbase + TILE_B + off);
        }
        #pragma unroll
        for (int nf2 = 0; nf2 < 2; ++nf2) {
            const uint32_t off = swz((uint32_t)((wn + nf2 * 16 + lrow) * 128 + kb));
            ldsm4(Bh[buf][nf2], sbase + 2 * TILE_B + off);
            ldsm4(Bl[buf][nf2], sbase + 3 * TILE_B + off);
        }
    };
    auto mma_all = [&](int buf) {
        #pragma unroll
        for (int mf = 0; mf < 4; ++mf) {
            #pragma unroll
            for (int nf = 0; nf < 4; ++nf) {
                const int p = nf >> 1, q = nf & 1;
                mma16816(acc[mf][nf], Ah[buf][mf], Bh[buf][p][q], Bh[buf][p][q + 2]);
                mma16816(acc[mf][nf], Ah[buf][mf], Bl[buf][p][q], Bl[buf][p][q + 2]);
                mma16816(acc[mf][nf], Al[buf][mf], Bh[buf][p][q], Bh[buf][p][q + 2]);
            }
        }
    };

    load_chunk(0, 0); cp_commit();
    if (NC > 1) { load_chunk(1, 1); cp_commit(); }

    for (int c = 0; c < NC; ++c) {
        if (c + 1 < NC) asm volatile("cp.async.wait_group 1;" ::: "memory");
        else            asm volatile("cp.async.wait_group 0;" ::: "memory");
        __syncthreads();

        const uint32_t sbase = sb + (uint32_t)(c % STAGES) * STAGE;
        const int cn = c + 2;
        const uint32_t nbase = sb + (uint32_t)(cn % STAGES) * STAGE;
        const bool has_next = cn < NC;

        ld_frag(0, sbase, 0);
        #pragma unroll
        for (int ks = 0; ks < 4; ++ks) {
            if (ks < 3) ld_frag((ks + 1) & 1, sbase, ks + 1);
            if (has_next) load_part(cn, nbase, ks);
            mma_all(ks & 1);
        }
        if (has_next) cp_commit();
        // no trailing barrier: the barrier at the top of iteration c+1 protects
        // stage reuse (writes for chunk c+3 are issued during iteration c+1,
        // after all warps finished reading stage c).
    }

    // Epilogue
    const int tig = l & 3, grp = l >> 2;
    #pragma unroll
    for (int nf = 0; nf < 4; ++nf) {
        const long col = n0 + wn + nf * 8 + 2 * tig;
        const float b0 = bias[col], b1 = bias[col + 1];
        #pragma unroll
        for (int mf = 0; mf < 4; ++mf) {
            const long r0 = m0 + wm + mf * 16 + grp;
            float v00 = acc[mf][nf][0] + b0, v01 = acc[mf][nf][1] + b1;
            float v10 = acc[mf][nf][2] + b0, v11 = acc[mf][nf][3] + b1;
            if (RELU) {
                v00 = fmaxf(v00, 0.f); v01 = fmaxf(v01, 0.f);
                v10 = fmaxf(v10, 0.f); v11 = fmaxf(v11, 0.f);
            }
            if (OUT_MODE == 0) {
                *reinterpret_cast<float2*>(Cf + r0 * (long)ldc + col) = make_float2(v00, v01);
                *reinterpret_cast<float2*>(Cf + (r0 + 8) * (long)ldc + col) = make_float2(v10, v11);
            } else {
                uint32_t h0, lo0, h1, lo1;
                split2(v00, v01, h0, lo0);
                split2(v10, v11, h1, lo1);
                *reinterpret_cast<uint32_t*>(Chi + r0 * (long)ldc + col) = h0;
                *reinterpret_cast<uint32_t*>(Clo + r0 * (long)ldc + col) = lo0;
                *reinterpret_cast<uint32_t*>(Chi + (r0 + 8) * (long)ldc + col) = h1;
                *reinterpret_cast<uint32_t*>(Clo + (r0 + 8) * (long)ldc + col) = lo1;
            }
        }
    }
}

// ---------------------------------------------------------------------------
// Launch
// ---------------------------------------------------------------------------
extern "C" void kernel_launch(void* const* d_in, const int* in_sizes, int n_in,
                              void* d_out, int out_size)
{
    const int*   ids   = (const int*)  d_in[0];
    const float* table = (const float*)d_in[1];
    const float* en_g  = (const float*)d_in[2];
    const float* en_b  = (const float*)d_in[3];
    const float* Wb    = (const float*)d_in[4];
    const float* bb    = (const float*)d_in[5];
    const float* cn_g  = (const float*)d_in[6];
    const float* cn_b  = (const float*)d_in[7];
    const float* tn_g  = (const float*)d_in[8];
    const float* tn_b  = (const float*)d_in[9];
    const float* out_W = (const float*)d_in[10];
    const float* out_b = (const float*)d_in[11];
    float* logits = (float*)d_out;

    __nv_bfloat16 *xhi, *xlo, *yhi, *ylo, *whi, *wlo, *owhi, *owlo;
    float *h2;
    cudaGetSymbolAddress((void**)&xhi,  g_xhi);
    cudaGetSymbolAddress((void**)&xlo,  g_xlo);
    cudaGetSymbolAddress((void**)&yhi,  g_yhi);
    cudaGetSymbolAddress((void**)&ylo,  g_ylo);
    cudaGetSymbolAddress((void**)&whi,  g_whi);
    cudaGetSymbolAddress((void**)&wlo,  g_wlo);
    cudaGetSymbolAddress((void**)&owhi, g_owhi);
    cudaGetSymbolAddress((void**)&owlo, g_owlo);
    cudaGetSymbolAddress((void**)&h2,   g_h2);

    cudaFuncSetAttribute(gemm_mma<true, 1>,  cudaFuncAttributeMaxDynamicSharedMemorySize, SMEM_SZ);
    cudaFuncSetAttribute(gemm_mma<true, 0>,  cudaFuncAttributeMaxDynamicSharedMemorySize, SMEM_SZ);
    cudaFuncSetAttribute(gemm_mma<false, 0>, cudaFuncAttributeMaxDynamicSharedMemorySize, SMEM_SZ);

    // 1) split weights into bf16 hi/lo
    f32_to_bf16pair<<<W_ELEMS / 4 / 256, 256>>>(
        (const float4*)Wb, (uint2*)whi, (uint2*)wlo, W_ELEMS / 4);
    f32_to_bf16pair<<<OW_ELEMS / 4 / 256, 256>>>(
        (const float4*)out_W, (uint2*)owhi, (uint2*)owlo, OW_ELEMS / 4);

    // 2) embedding + LN
    embed_ln_kernel<<<NTOK, 128>>>(ids, table, en_g, en_b);

    // 3) three residual blocks
    const dim3 fnn_grid(H / BN, NTOK / BM);           // (8, 32)
    for (int bi = 0; bi < 3; ++bi) {
        const __nv_bfloat16* W0h = whi + (long)(bi * 2 + 0) * H * H;
        const __nv_bfloat16* W0l = wlo + (long)(bi * 2 + 0) * H * H;
        const __nv_bfloat16* W1h = whi + (long)(bi * 2 + 1) * H * H;
        const __nv_bfloat16* W1l = wlo + (long)(bi * 2 + 1) * H * H;
        const float* b0 = bb + (bi * 2 + 0) * H;
        const float* b1 = bb + (bi * 2 + 1) * H;

        gemm_mma<true, 1><<<fnn_grid, 256, SMEM_SZ>>>(
            xhi, xlo, H, W0h, W0l, H, b0,
            (float*)nullptr, yhi, ylo, H, H);
        gemm_mma<true, 0><<<fnn_grid, 256, SMEM_SZ>>>(
            yhi, ylo, H, W1h, W1l, H, b1,
            h2, (__nv_bfloat16*)nullptr, (__nv_bfloat16*)nullptr, H, H);
        resid_ln_kernel<<<dim3(NTOK, 2), 128>>>(cn_g + bi * C, cn_b + bi * C,
                                                tn_g + bi * E, tn_b + bi * E);
    }

    // 4) logits = tok @ out_W^T + out_b
    const dim3 out_grid(V / BN, NTOK / BM);           // (250, 32)
    gemm_mma<false, 0><<<out_grid, 256, SMEM_SZ>>>(
        xhi + C, xlo + C, H, owhi, owlo, C, out_b,
        logits, (__nv_bfloat16*)nullptr, (__nv_bfloat16*)nullptr, V, C);
}